// round 2
// baseline (speedup 1.0000x reference)
#include <cuda_runtime.h>
#include <math.h>

#define L_SEQ   2048
#define EMB     1024
#define NHEAD   16
#define HD      64
#define BATCH   2
#define M_ROWS  (BATCH * L_SEQ)   /* 4096 */
#define QKV_N   (3 * EMB)         /* 3072 */

// Scratch (allocation-free): qkv activations + attention output
__device__ float g_qkv[(size_t)M_ROWS * QKV_N];   // 48 MB
__device__ float g_att[(size_t)M_ROWS * EMB];     // 16 MB

// ---------------------------------------------------------------------------
// fp32 SGEMM: C[M,N] = A[M,K] @ B[K,N] + bias[N]
// 128x128 block tile, K-step 8, 256 threads, 8x8 per-thread microtile.
// Assumes M%128==0, N%128==0, K%8==0 (true for all three calls).
// ---------------------------------------------------------------------------
__device__ __forceinline__ void sgemm_body(const float* __restrict__ A,
                                           const float* __restrict__ B,
                                           const float* __restrict__ bias,
                                           float* __restrict__ C,
                                           int M, int N, int K)
{
    __shared__ float As[8][132];   // As[k][m] (transposed), padded
    __shared__ float Bs[8][132];   // Bs[k][n], padded

    const int tid = threadIdx.x;
    const int bm = blockIdx.y * 128;
    const int bn = blockIdx.x * 128;

    const int tx = tid % 16;       // n microtile
    const int ty = tid / 16;       // m microtile

    // A load mapping: 128 rows x 8 cols = 256 float4 (2 per row)
    const int arow  = tid >> 1;            // 0..127
    const int acol4 = (tid & 1) * 4;       // 0 or 4
    // B load mapping: 8 rows x 128 cols = 256 float4
    const int brow = tid >> 5;             // 0..7
    const int bcol = (tid & 31) * 4;       // 0..124

    float acc[8][8];
#pragma unroll
    for (int i = 0; i < 8; i++)
#pragma unroll
        for (int j = 0; j < 8; j++) acc[i][j] = 0.f;

    for (int k0 = 0; k0 < K; k0 += 8) {
        float4 a4 = *(const float4*)(A + (size_t)(bm + arow) * K + k0 + acol4);
        float4 b4 = *(const float4*)(B + (size_t)(k0 + brow) * N + bn + bcol);
        __syncthreads();   // previous tile's compute done before overwrite
        As[acol4 + 0][arow] = a4.x;
        As[acol4 + 1][arow] = a4.y;
        As[acol4 + 2][arow] = a4.z;
        As[acol4 + 3][arow] = a4.w;
        *(float4*)&Bs[brow][bcol] = b4;
        __syncthreads();

#pragma unroll
        for (int kk = 0; kk < 8; kk++) {
            float a[8], b[8];
#pragma unroll
            for (int i = 0; i < 8; i++) a[i] = As[kk][ty * 8 + i];
#pragma unroll
            for (int j = 0; j < 8; j++) b[j] = Bs[kk][tx * 8 + j];
#pragma unroll
            for (int i = 0; i < 8; i++)
#pragma unroll
                for (int j = 0; j < 8; j++)
                    acc[i][j] += a[i] * b[j];
        }
    }

#pragma unroll
    for (int i = 0; i < 8; i++) {
        int m = bm + ty * 8 + i;
#pragma unroll
        for (int j = 0; j < 8; j += 4) {
            int n = bn + tx * 8 + j;
            float4 r;
            r.x = acc[i][j + 0] + bias[n + 0];
            r.y = acc[i][j + 1] + bias[n + 1];
            r.z = acc[i][j + 2] + bias[n + 2];
            r.w = acc[i][j + 3] + bias[n + 3];
            *(float4*)(C + (size_t)m * N + n) = r;
        }
    }
}

__global__ __launch_bounds__(256) void gemm_qkv_kernel(const float* __restrict__ x,
                                                       const float* __restrict__ w,
                                                       const float* __restrict__ bias)
{
    sgemm_body(x, w, bias, g_qkv, M_ROWS, QKV_N, EMB);
}

__global__ __launch_bounds__(256) void gemm_out_kernel(const float* __restrict__ w,
                                                       const float* __restrict__ bias,
                                                       float* __restrict__ out)
{
    sgemm_body(g_att, w, bias, out, M_ROWS, EMB, EMB);
}

// ---------------------------------------------------------------------------
// Yat causal attention, fp32 streaming (flash-style online softmax).
// Grid: (L/128, NHEAD, BATCH); block: 128 threads; thread t owns query row
// q_idx = blockIdx.x*128 + t.  score = dot^2 / (|q|^2 + |k|^2 - 2*dot + eps).
// ---------------------------------------------------------------------------
__global__ __launch_bounds__(128) void yat_attn_kernel()
{
    const int qt = blockIdx.x;
    const int h  = blockIdx.y;
    const int b  = blockIdx.z;
    const int t  = threadIdx.x;
    const int q_idx = qt * 128 + t;

    // load q (64 floats) into registers, compute |q|^2
    const float* qp = g_qkv + (size_t)(b * L_SEQ + q_idx) * QKV_N + h * HD;
    float q[HD];
    float qn = 0.f;
#pragma unroll
    for (int d4 = 0; d4 < HD; d4 += 4) {
        float4 v = *(const float4*)(qp + d4);
        q[d4 + 0] = v.x; q[d4 + 1] = v.y; q[d4 + 2] = v.z; q[d4 + 3] = v.w;
        qn += v.x * v.x + v.y * v.y + v.z * v.z + v.w * v.w;
    }

    float m = -1e30f, l = 0.f;
    float o[HD];
#pragma unroll
    for (int d = 0; d < HD; d++) o[d] = 0.f;

    __shared__ float Ks[64][68];
    __shared__ float Vs[64][68];
    __shared__ float kns[64];

    const int ktiles = 2 * qt + 2;   // covers keys [0, qt*128+128)
    for (int kt = 0; kt < ktiles; kt++) {
        const int k0 = kt * 64;
        __syncthreads();
        // cooperative load: 64 keys x 64 dims for K and V, float4-vectorized
        for (int i = t; i < 64 * 16; i += 128) {
            int row = i >> 4;         // key within tile
            int c4  = (i & 15) * 4;   // dim start
            const float* kp = g_qkv + (size_t)(b * L_SEQ + k0 + row) * QKV_N
                              + EMB + h * HD + c4;
            float4 kv = *(const float4*)kp;
            float4 vv = *(const float4*)(kp + EMB);
            Ks[row][c4 + 0] = kv.x; Ks[row][c4 + 1] = kv.y;
            Ks[row][c4 + 2] = kv.z; Ks[row][c4 + 3] = kv.w;
            Vs[row][c4 + 0] = vv.x; Vs[row][c4 + 1] = vv.y;
            Vs[row][c4 + 2] = vv.z; Vs[row][c4 + 3] = vv.w;
        }
        __syncthreads();
        if (t < 64) {
            float s = 0.f;
#pragma unroll
            for (int d = 0; d < HD; d++) s += Ks[t][d] * Ks[t][d];
            kns[t] = s;
        }
        __syncthreads();

        for (int j = 0; j < 64; j++) {
            int kg = k0 + j;
            if (kg > q_idx) break;    // causal: remaining keys in tile masked
            float dot = 0.f;
#pragma unroll
            for (int d = 0; d < HD; d++) dot += q[d] * Ks[j][d];
            float denom = qn + kns[j] - 2.f * dot + 1e-6f;
            float s = (dot * dot) / denom;
            if (s > m) {
                float scale = __expf(m - s);
                m = s;
                l = l * scale + 1.f;
#pragma unroll
                for (int d = 0; d < HD; d++) o[d] = o[d] * scale + Vs[j][d];
            } else {
                float p = __expf(s - m);
                l += p;
#pragma unroll
                for (int d = 0; d < HD; d++) o[d] += p * Vs[j][d];
            }
        }
    }

    const float inv = 1.f / l;
    float* op = g_att + (size_t)(b * L_SEQ + q_idx) * EMB + h * HD;
#pragma unroll
    for (int d4 = 0; d4 < HD; d4 += 4) {
        float4 r;
        r.x = o[d4 + 0] * inv; r.y = o[d4 + 1] * inv;
        r.z = o[d4 + 2] * inv; r.w = o[d4 + 3] * inv;
        *(float4*)(op + d4) = r;
    }
}

// ---------------------------------------------------------------------------
extern "C" void kernel_launch(void* const* d_in, const int* in_sizes, int n_in,
                              void* d_out, int out_size)
{
    const float* x     = (const float*)d_in[0];
    const float* w_qkv = (const float*)d_in[1];
    const float* b_qkv = (const float*)d_in[2];
    const float* w_out = (const float*)d_in[3];
    const float* b_out = (const float*)d_in[4];
    float* out = (float*)d_out;

    // 1) QKV projection: [4096,1024] @ [1024,3072]
    {
        dim3 grid(QKV_N / 128, M_ROWS / 128);
        gemm_qkv_kernel<<<grid, 256>>>(x, w_qkv, b_qkv);
    }
    // 2) Yat causal attention
    {
        dim3 grid(L_SEQ / 128, NHEAD, BATCH);
        yat_attn_kernel<<<grid, 128>>>();
    }
    // 3) Output projection: [4096,1024] @ [1024,1024]
    {
        dim3 grid(EMB / 128, M_ROWS / 128);
        gemm_out_kernel<<<grid, 256>>>(w_out, b_out, out);
    }
}

// round 4
// speedup vs baseline: 1.3004x; 1.3004x over previous
#include <cuda_runtime.h>
#include <math.h>

#define L_SEQ   2048
#define EMB     1024
#define NHEAD   16
#define HD      64
#define BATCH   2
#define M_ROWS  (BATCH * L_SEQ)   /* 4096 */
#define QKV_N   (3 * EMB)         /* 3072 */

#define BQ 64
#define BK 32

// Scratch (allocation-free): qkv activations + attention output
__device__ float g_qkv[(size_t)M_ROWS * QKV_N];   // 48 MB
__device__ float g_att[(size_t)M_ROWS * EMB];     // 16 MB

// ---------------------------------------------------------------------------
// fp32 SGEMM: C[M,N] = A[M,K] @ B[K,N] + bias[N]
// 128x128 tile, K-step 8, 256 threads, 8x8 microtile, double-buffered smem.
// Assumes M%128==0, N%128==0, K%8==0 (true for all three calls).
// ---------------------------------------------------------------------------
__device__ __forceinline__ void sgemm_body(const float* __restrict__ A,
                                           const float* __restrict__ B,
                                           const float* __restrict__ bias,
                                           float* __restrict__ C,
                                           int M, int N, int K)
{
    __shared__ __align__(16) float As[2][8][132];   // [buf][k][m] transposed
    __shared__ __align__(16) float Bs[2][8][132];   // [buf][k][n]

    const int tid = threadIdx.x;
    const int bm = blockIdx.y * 128;
    const int bn = blockIdx.x * 128;

    const int tx = tid % 16;
    const int ty = tid / 16;

    const int arow  = tid >> 1;            // 0..127
    const int acol4 = (tid & 1) * 4;       // 0 or 4
    const int brow = tid >> 5;             // 0..7
    const int bcol = (tid & 31) * 4;       // 0..124

    float acc[8][8];
#pragma unroll
    for (int i = 0; i < 8; i++)
#pragma unroll
        for (int j = 0; j < 8; j++) acc[i][j] = 0.f;

    // preload tile 0
    float4 a4 = *(const float4*)(A + (size_t)(bm + arow) * K + acol4);
    float4 b4 = *(const float4*)(B + (size_t)brow * N + bn + bcol);
    As[0][acol4 + 0][arow] = a4.x;
    As[0][acol4 + 1][arow] = a4.y;
    As[0][acol4 + 2][arow] = a4.z;
    As[0][acol4 + 3][arow] = a4.w;
    *(float4*)&Bs[0][brow][bcol] = b4;
    __syncthreads();

    int cur = 0;
    for (int k0 = 0; k0 < K; k0 += 8) {
        const int nxt = cur ^ 1;
        const bool more = (k0 + 8 < K);
        if (more) {
            a4 = *(const float4*)(A + (size_t)(bm + arow) * K + k0 + 8 + acol4);
            b4 = *(const float4*)(B + (size_t)(k0 + 8 + brow) * N + bn + bcol);
        }

#pragma unroll
        for (int kk = 0; kk < 8; kk++) {
            float a[8], b[8];
#pragma unroll
            for (int h4 = 0; h4 < 2; h4++) {
                float4 t = *(const float4*)&As[cur][kk][ty * 8 + h4 * 4];
                a[h4*4+0]=t.x; a[h4*4+1]=t.y; a[h4*4+2]=t.z; a[h4*4+3]=t.w;
            }
#pragma unroll
            for (int h4 = 0; h4 < 2; h4++) {
                float4 t = *(const float4*)&Bs[cur][kk][tx * 8 + h4 * 4];
                b[h4*4+0]=t.x; b[h4*4+1]=t.y; b[h4*4+2]=t.z; b[h4*4+3]=t.w;
            }
#pragma unroll
            for (int i = 0; i < 8; i++)
#pragma unroll
                for (int j = 0; j < 8; j++)
                    acc[i][j] += a[i] * b[j];
        }

        if (more) {
            As[nxt][acol4 + 0][arow] = a4.x;
            As[nxt][acol4 + 1][arow] = a4.y;
            As[nxt][acol4 + 2][arow] = a4.z;
            As[nxt][acol4 + 3][arow] = a4.w;
            *(float4*)&Bs[nxt][brow][bcol] = b4;
        }
        __syncthreads();
        cur = nxt;
    }

#pragma unroll
    for (int i = 0; i < 8; i++) {
        int m = bm + ty * 8 + i;
#pragma unroll
        for (int j = 0; j < 8; j += 4) {
            int n = bn + tx * 8 + j;
            float4 r;
            r.x = acc[i][j + 0] + bias[n + 0];
            r.y = acc[i][j + 1] + bias[n + 1];
            r.z = acc[i][j + 2] + bias[n + 2];
            r.w = acc[i][j + 3] + bias[n + 3];
            *(float4*)(C + (size_t)m * N + n) = r;
        }
    }
}

__global__ __launch_bounds__(256, 2) void gemm_qkv_kernel(const float* __restrict__ x,
                                                          const float* __restrict__ w,
                                                          const float* __restrict__ bias)
{
    sgemm_body(x, w, bias, g_qkv, M_ROWS, QKV_N, EMB);
}

__global__ __launch_bounds__(256, 2) void gemm_out_kernel(const float* __restrict__ w,
                                                          const float* __restrict__ bias,
                                                          float* __restrict__ out)
{
    sgemm_body(g_att, w, bias, out, M_ROWS, EMB, EMB);
}

// ---------------------------------------------------------------------------
// Yat causal attention, block-tiled flash style.
// Block: 256 threads (16x16). Tile: BQ=64 queries x BK=32 keys.
// S microtile 4x2 per thread; O microtile 4 rows x 4 dims per thread.
// score = dot^2 / (|q|^2 + |k|^2 - 2*dot + eps), causal mask, online softmax.
// ---------------------------------------------------------------------------
__global__ __launch_bounds__(256) void yat_attn_kernel()
{
    __shared__ __align__(16) float Qs[BQ][68];
    __shared__ __align__(16) float Ks[BK][68];
    __shared__ __align__(16) float Vs[BK][68];
    __shared__ __align__(16) float Ps[BK][68];   // P transposed: Ps[j][i]
    __shared__ float red[BQ][17];
    __shared__ float qn[BQ], mrow[BQ], lrow[BQ], arow[BQ];
    __shared__ float kn[BK];

    const int qt = blockIdx.x;
    const int h  = blockIdx.y;
    const int b  = blockIdx.z;
    const int tid = threadIdx.x;
    const int tx = tid & 15;
    const int ty = tid >> 4;
    const int i0 = ty * 4;      // query rows owned
    const int j0 = tx * 2;      // S key cols owned
    const int d0 = tx * 4;      // O dims owned
    const int qbase = qt * BQ;

    const float* qkv_b = g_qkv + (size_t)b * L_SEQ * QKV_N;

    // Load Q tile (64 x 64), 4 float4 per thread
    for (int it = tid; it < BQ * 16; it += 256) {
        int r = it >> 4, c4 = (it & 15) * 4;
        *(float4*)&Qs[r][c4] =
            *(const float4*)(qkv_b + (size_t)(qbase + r) * QKV_N + h * HD + c4);
    }
    __syncthreads();
    if (tid < BQ) {
        float s = 0.f;
#pragma unroll
        for (int d = 0; d < HD; d++) s += Qs[tid][d] * Qs[tid][d];
        qn[tid] = s;
        mrow[tid] = -1e30f;
        lrow[tid] = 0.f;
    }

    float o[4][4];
#pragma unroll
    for (int i = 0; i < 4; i++)
#pragma unroll
        for (int d = 0; d < 4; d++) o[i][d] = 0.f;

    const int nkt = 2 * qt + 2;
    for (int kt = 0; kt < nkt; kt++) {
        const int k0 = kt * BK;
        const bool diag = (kt >= 2 * qt);
        __syncthreads();   // prior PV done before K/V overwrite; qn/m/l ready (kt=0)

        // Load K,V tiles (32 x 64 each), 2 float4 per thread per array
        for (int it = tid; it < BK * 16; it += 256) {
            int r = it >> 4, c4 = (it & 15) * 4;
            const float* kp = qkv_b + (size_t)(k0 + r) * QKV_N + EMB + h * HD + c4;
            *(float4*)&Ks[r][c4] = *(const float4*)kp;
            *(float4*)&Vs[r][c4] = *(const float4*)(kp + EMB);
        }
        __syncthreads();
        if (tid < BK) {
            float s = 0.f;
#pragma unroll
            for (int d = 0; d < HD; d++) s += Ks[tid][d] * Ks[tid][d];
            kn[tid] = s;
        }
        __syncthreads();

        // S = Q K^T, 4x2 microtile
        float s_[4][2];
#pragma unroll
        for (int i = 0; i < 4; i++) { s_[i][0] = 0.f; s_[i][1] = 0.f; }
#pragma unroll
        for (int d = 0; d < HD; d += 4) {
            float4 k0v = *(const float4*)&Ks[j0 + 0][d];
            float4 k1v = *(const float4*)&Ks[j0 + 1][d];
#pragma unroll
            for (int i = 0; i < 4; i++) {
                float4 qv = *(const float4*)&Qs[i0 + i][d];
                s_[i][0] += qv.x * k0v.x + qv.y * k0v.y + qv.z * k0v.z + qv.w * k0v.w;
                s_[i][1] += qv.x * k1v.x + qv.y * k1v.y + qv.z * k1v.z + qv.w * k1v.w;
            }
        }

        // Yat transform + causal mask
        float sc[4][2];
#pragma unroll
        for (int i = 0; i < 4; i++) {
            float qni = qn[i0 + i];
#pragma unroll
            for (int j = 0; j < 2; j++) {
                float dot = s_[i][j];
                float denom = qni + kn[j0 + j] - 2.f * dot + 1e-6f;
                float v = (dot * dot) / denom;
                if (diag && (k0 + j0 + j > qbase + i0 + i)) v = -1e30f;
                sc[i][j] = v;
            }
        }

        // Row max reduce
#pragma unroll
        for (int i = 0; i < 4; i++)
            red[i0 + i][tx] = fmaxf(sc[i][0], sc[i][1]);
        __syncthreads();
        if (tid < BQ) {
            float mx = red[tid][0];
#pragma unroll
            for (int t = 1; t < 16; t++) mx = fmaxf(mx, red[tid][t]);
            float mo = mrow[tid];
            float mn = fmaxf(mo, mx);
            float al = __expf(mo - mn);
            mrow[tid] = mn;
            arow[tid] = al;
            lrow[tid] *= al;
        }
        __syncthreads();

        // P = exp(sc - m), store transposed, partial row sums
        float p[4][2];
        float psum[4];
#pragma unroll
        for (int i = 0; i < 4; i++) {
            float mi = mrow[i0 + i];
            p[i][0] = __expf(sc[i][0] - mi);
            p[i][1] = __expf(sc[i][1] - mi);
            psum[i] = p[i][0] + p[i][1];
        }
        {
            float4 c0 = make_float4(p[0][0], p[1][0], p[2][0], p[3][0]);
            float4 c1 = make_float4(p[0][1], p[1][1], p[2][1], p[3][1]);
            *(float4*)&Ps[j0 + 0][i0] = c0;
            *(float4*)&Ps[j0 + 1][i0] = c1;
        }
#pragma unroll
        for (int i = 0; i < 4; i++)
            red[i0 + i][tx] = psum[i];
        __syncthreads();
        if (tid < BQ) {
            float s = red[tid][0];
#pragma unroll
            for (int t = 1; t < 16; t++) s += red[tid][t];
            lrow[tid] += s;
        }

        // Rescale O and accumulate PV
        float a_[4];
#pragma unroll
        for (int i = 0; i < 4; i++) a_[i] = arow[i0 + i];
#pragma unroll
        for (int i = 0; i < 4; i++)
#pragma unroll
            for (int d = 0; d < 4; d++) o[i][d] *= a_[i];

#pragma unroll 8
        for (int j = 0; j < BK; j++) {
            float4 pv = *(const float4*)&Ps[j][i0];
            float4 vv = *(const float4*)&Vs[j][d0];
            o[0][0] += pv.x * vv.x; o[0][1] += pv.x * vv.y;
            o[0][2] += pv.x * vv.z; o[0][3] += pv.x * vv.w;
            o[1][0] += pv.y * vv.x; o[1][1] += pv.y * vv.y;
            o[1][2] += pv.y * vv.z; o[1][3] += pv.y * vv.w;
            o[2][0] += pv.z * vv.x; o[2][1] += pv.z * vv.y;
            o[2][2] += pv.z * vv.z; o[2][3] += pv.z * vv.w;
            o[3][0] += pv.w * vv.x; o[3][1] += pv.w * vv.y;
            o[3][2] += pv.w * vv.z; o[3][3] += pv.w * vv.w;
        }
    }
    __syncthreads();   // final lrow update visible

    float* ob = g_att + (size_t)(b * L_SEQ + qbase) * EMB + h * HD;
#pragma unroll
    for (int i = 0; i < 4; i++) {
        float inv = 1.f / lrow[i0 + i];
        float4 r;
        r.x = o[i][0] * inv; r.y = o[i][1] * inv;
        r.z = o[i][2] * inv; r.w = o[i][3] * inv;
        *(float4*)(ob + (size_t)(i0 + i) * EMB + d0) = r;
    }
}

// ---------------------------------------------------------------------------
extern "C" void kernel_launch(void* const* d_in, const int* in_sizes, int n_in,
                              void* d_out, int out_size)
{
    const float* x     = (const float*)d_in[0];
    const float* w_qkv = (const float*)d_in[1];
    const float* b_qkv = (const float*)d_in[2];
    const float* w_out = (const float*)d_in[3];
    const float* b_out = (const float*)d_in[4];
    float* out = (float*)d_out;

    {
        dim3 grid(QKV_N / 128, M_ROWS / 128);
        gemm_qkv_kernel<<<grid, 256>>>(x, w_qkv, b_qkv);
    }
    {
        dim3 grid(L_SEQ / BQ, NHEAD, BATCH);
        yat_attn_kernel<<<grid, 256>>>();
    }
    {
        dim3 grid(EMB / 128, M_ROWS / 128);
        gemm_out_kernel<<<grid, 256>>>(w_out, b_out, out);
    }
}